// round 4
// baseline (speedup 1.0000x reference)
#include <cuda_runtime.h>

typedef unsigned long long ull;

#define BB   8
#define NP   4096
#define CI   64
#define CO   64
#define KK   20

// ---------------- scratch (static device globals; no runtime allocation) ----
static __device__ float g_dist[(size_t)BB * NP * NP];   // 512 MB score rows
static __device__ float g_xx[BB * NP];                  // squared norms
static __device__ int   g_idx[BB * NP * KK];            // knn indices
static __device__ float g_a [BB * NP * CO];             // (W1-W2) @ x_n
static __device__ float g_cc[BB * NP * CO];             // W2 @ x_m
static __device__ float g_hmax[(size_t)BB * NP * CO];
static __device__ float g_hmin[(size_t)BB * NP * CO];
static __device__ float g_sum[CO];
static __device__ float g_sumsq[CO];
static __device__ float g_scale[CO];
static __device__ float g_bias[CO];

// ---------------- helpers ---------------------------------------------------
__device__ __forceinline__ ull ffma2(ull a, ull b, ull c) {
    ull d;
    asm("fma.rn.f32x2 %0, %1, %2, %3;" : "=l"(d) : "l"(a), "l"(b), "l"(c));
    return d;
}
__device__ __forceinline__ ull pack2(float lo, float hi) {
    return (ull)__float_as_uint(lo) | ((ull)__float_as_uint(hi) << 32);
}

// ---------------- 0: zero channel stats -------------------------------------
__global__ void zero_stats_k() {
    int t = threadIdx.x;
    if (t < CO) { g_sum[t] = 0.f; g_sumsq[t] = 0.f; }
}

// ---------------- 1: squared norms ------------------------------------------
__global__ void xx_k(const float* __restrict__ x) {
    int g = blockIdx.x * blockDim.x + threadIdx.x;     // 0..BB*NP-1
    int b = g >> 12;
    int n = g & (NP - 1);
    const float* xb = x + (size_t)b * CI * NP + n;
    float s = 0.f;
    #pragma unroll
    for (int c = 0; c < CI; ++c) { float v = xb[c * NP]; s = fmaf(v, v, s); }
    g_xx[g] = s;
}

// ---------------- 2: a = (W1-W2)@x_n,  c = W2@x_n ---------------------------
__global__ __launch_bounds__(256) void ac_k(const float* __restrict__ x,
                                            const float* __restrict__ W) {
    __shared__ float sWd[CI * CO];   // [c][o]
    __shared__ float sW2[CI * CO];   // [c][o]
    int tid = threadIdx.x;
    for (int i = tid; i < CI * CO; i += 256) {
        int o = i >> 6, c = i & 63;
        float w1 = W[o * 128 + c];
        float w2 = W[o * 128 + 64 + c];
        sWd[c * CO + o] = w1 - w2;
        sW2[c * CO + o] = w2;
    }
    __syncthreads();
    int b  = blockIdx.y;
    int n  = blockIdx.x * 128 + (tid & 127);
    int o0 = (tid >> 7) * 32;
    float aa[32], cc[32];
    #pragma unroll
    for (int j = 0; j < 32; ++j) { aa[j] = 0.f; cc[j] = 0.f; }
    const float* xb = x + (size_t)b * CI * NP + n;
    for (int c = 0; c < CI; ++c) {
        float xv = xb[c * NP];
        const float4* wd4 = (const float4*)(sWd + c * CO + o0);
        const float4* w24 = (const float4*)(sW2 + c * CO + o0);
        #pragma unroll
        for (int j4 = 0; j4 < 8; ++j4) {
            float4 wd = wd4[j4], w2 = w24[j4];
            aa[j4*4+0] = fmaf(xv, wd.x, aa[j4*4+0]);
            aa[j4*4+1] = fmaf(xv, wd.y, aa[j4*4+1]);
            aa[j4*4+2] = fmaf(xv, wd.z, aa[j4*4+2]);
            aa[j4*4+3] = fmaf(xv, wd.w, aa[j4*4+3]);
            cc[j4*4+0] = fmaf(xv, w2.x, cc[j4*4+0]);
            cc[j4*4+1] = fmaf(xv, w2.y, cc[j4*4+1]);
            cc[j4*4+2] = fmaf(xv, w2.z, cc[j4*4+2]);
            cc[j4*4+3] = fmaf(xv, w2.w, cc[j4*4+3]);
        }
    }
    size_t base = ((size_t)b * NP + n) * CO + o0;
    #pragma unroll
    for (int j = 0; j < 32; ++j) { g_a[base + j] = aa[j]; g_cc[base + j] = cc[j]; }
}

// ---------------- 3: Gram scores  s = inner(n,m) - 0.5*xx[m] ----------------
// 128x128 tile, c-chunked (2x32), 8n x 8m microtile with f32x2 packed FMAs.
__global__ __launch_bounds__(256) void gram_k(const float* __restrict__ x) {
    __shared__ float sQ [32 * 128];   // [c][128] queries (n tile)
    __shared__ ull   sP2[32 * 64];    // [c][64]  point pairs (m tile)
    __shared__ float sXX[128];
    const int tid = threadIdx.x;
    const int b  = blockIdx.z;
    const int n0 = blockIdx.y << 7;
    const int m0 = blockIdx.x << 7;
    const float* xb = x + (size_t)b * CI * NP;
    if (tid < 128) sXX[tid] = 0.5f * g_xx[b * NP + m0 + tid];

    const int tx = tid & 15;      // m-pair:  p = tx + 16*g  ->  m = 2p,2p+1
    const int ty = tid >> 4;      // n:       n = n0 + ty*8 + i
    ull acc[8][4];
    #pragma unroll
    for (int i = 0; i < 8; ++i)
        #pragma unroll
        for (int g = 0; g < 4; ++g) acc[i][g] = 0ull;

    for (int cc = 0; cc < CI; cc += 32) {
        __syncthreads();
        for (int i = tid; i < 32 * 32; i += 256) {
            int c = i >> 5, j = i & 31;
            float4 v = *(const float4*)(xb + (size_t)(cc + c) * NP + n0 + (j << 2));
            *(float4*)(sQ + c * 128 + (j << 2)) = v;
            float4 w = *(const float4*)(xb + (size_t)(cc + c) * NP + m0 + (j << 2));
            sP2[c * 64 + (j << 1)    ] = pack2(w.x, w.y);
            sP2[c * 64 + (j << 1) + 1] = pack2(w.z, w.w);
        }
        __syncthreads();
        #pragma unroll 4
        for (int c = 0; c < 32; ++c) {
            ull q[8], p[4];
            #pragma unroll
            for (int i = 0; i < 8; ++i) {
                unsigned u = __float_as_uint(sQ[c * 128 + ty * 8 + i]);
                q[i] = (ull)u | ((ull)u << 32);
            }
            #pragma unroll
            for (int g = 0; g < 4; ++g) p[g] = sP2[c * 64 + tx + (g << 4)];
            #pragma unroll
            for (int i = 0; i < 8; ++i)
                #pragma unroll
                for (int g = 0; g < 4; ++g) acc[i][g] = ffma2(q[i], p[g], acc[i][g]);
        }
    }
    size_t rb = (size_t)b * NP + n0 + ty * 8;
    #pragma unroll
    for (int g = 0; g < 4; ++g) {
        int mp = tx + (g << 4);
        float2 hx = *(const float2*)(sXX + (mp << 1));
        #pragma unroll
        for (int i = 0; i < 8; ++i) {
            float lo = __uint_as_float((unsigned)(acc[i][g]));
            float hi = __uint_as_float((unsigned)(acc[i][g] >> 32));
            float2 v; v.x = lo - hx.x; v.y = hi - hx.y;
            *(float2*)(g_dist + (rb + i) * NP + m0 + (mp << 1)) = v;
        }
    }
}

// ---------------- 4: top-20 per row (warp/row, chunked argmax-remove) -------
__global__ __launch_bounds__(256) void select_k() {
    int wg   = (blockIdx.x * 256 + threadIdx.x) >> 5;  // row id b*NP+n
    int lane = threadIdx.x & 31;
    float* row = g_dist + (size_t)wg * NP;
    const float NEG = __int_as_float(0xff800000);      // -inf

    float cmax[8]; int carg[8];
    #pragma unroll
    for (int t = 0; t < 8; ++t) {
        float bv = NEG; int ba = 0;
        #pragma unroll
        for (int jj = 0; jj < 16; ++jj) {
            int m = ((t * 16 + jj) << 5) + lane;
            float v = row[m];
            if (v > bv) { bv = v; ba = m; }
        }
        cmax[t] = bv; carg[t] = ba;
    }

    int* op = g_idx + (size_t)wg * KK;
    for (int r = 0; r < KK; ++r) {
        float v = cmax[0]; int a = carg[0];
        #pragma unroll
        for (int t = 1; t < 8; ++t) if (cmax[t] > v) { v = cmax[t]; a = carg[t]; }
        #pragma unroll
        for (int off = 16; off; off >>= 1) {
            float ov = __shfl_xor_sync(0xffffffffu, v, off);
            int   oa = __shfl_xor_sync(0xffffffffu, a, off);
            if (ov > v || (ov == v && oa < a)) { v = ov; a = oa; }
        }
        if (lane == 0) op[r] = a;
        if ((a & 31) == lane) {
            row[a] = NEG;
            int tw = a >> 9;                 // (a>>5)>>4
            #pragma unroll
            for (int t = 0; t < 8; ++t) if (t == tw) {
                float bv = NEG; int ba = 0;
                #pragma unroll
                for (int jj = 0; jj < 16; ++jj) {
                    int m = ((t * 16 + jj) << 5) + lane;
                    float vv = row[m];
                    if (vv > bv) { bv = vv; ba = m; }
                }
                cmax[t] = bv; carg[t] = ba;
            }
        }
    }
}

// ---------------- 5: per-(b,n,o) max/min over k + channel stats -------------
__global__ __launch_bounds__(256) void maxmin_k() {
    __shared__ float sSum[CO], sSq[CO];
    int tid = threadIdx.x;
    if (tid < CO) { sSum[tid] = 0.f; sSq[tid] = 0.f; }
    __syncthreads();
    int o = tid & 63;
    int r = blockIdx.x * 4 + (tid >> 6);       // row = b*NP+n
    int b = r >> 12;
    float av = g_a[(size_t)r * CO + o];
    const int* ip = g_idx + (size_t)r * KK;
    const float PINF = __int_as_float(0x7f800000);
    float mx = -PINF, mn = PINF, s = 0.f, s2 = 0.f;
    #pragma unroll
    for (int k = 0; k < KK; ++k) {
        int j = ip[k];
        float e = av + g_cc[((size_t)(b << 12) + j) * CO + o];
        mx = fmaxf(mx, e); mn = fminf(mn, e);
        s += e; s2 = fmaf(e, e, s2);
    }
    g_hmax[(size_t)r * CO + o] = mx;
    g_hmin[(size_t)r * CO + o] = mn;
    atomicAdd(&sSum[o], s);
    atomicAdd(&sSq[o], s2);
    __syncthreads();
    if (tid < CO) {
        atomicAdd(&g_sum[tid], sSum[tid]);
        atomicAdd(&g_sumsq[tid], sSq[tid]);
    }
}

// ---------------- 6: finalize batchnorm affine ------------------------------
__global__ void finalize_k(const float* __restrict__ gamma,
                           const float* __restrict__ beta) {
    int o = threadIdx.x;
    const float cnt = (float)BB * NP * KK;
    float mean = g_sum[o] / cnt;
    float var  = g_sumsq[o] / cnt - mean * mean;
    float sc   = gamma[o] * rsqrtf(var + 1e-5f);
    g_scale[o] = sc;
    g_bias[o]  = fmaf(-mean, sc, beta[o]);
}

// ---------------- 7: output (affine + leaky + transpose to (B,CO,N)) --------
__global__ __launch_bounds__(256) void out_k(float* __restrict__ out) {
    __shared__ float sm[64][65];
    int tid = threadIdx.x;
    int b = blockIdx.y, n0 = blockIdx.x * 64;
    #pragma unroll
    for (int it = 0; it < 16; ++it) {
        int i = it * 4 + (tid >> 6), o = tid & 63;
        float sc = g_scale[o];
        size_t idx = ((size_t)b * NP + n0 + i) * CO + o;
        float h = (sc >= 0.f) ? g_hmax[idx] : g_hmin[idx];
        float v = fmaf(sc, h, g_bias[o]);
        sm[i][o] = (v >= 0.f) ? v : 0.2f * v;
    }
    __syncthreads();
    #pragma unroll
    for (int it = 0; it < 16; ++it) {
        int o = it * 4 + (tid >> 6), n = tid & 63;
        out[((size_t)b * CO + o) * NP + n0 + n] = sm[n][o];
    }
}

// ---------------- launch -----------------------------------------------------
extern "C" void kernel_launch(void* const* d_in, const int* in_sizes, int n_in,
                              void* d_out, int out_size) {
    const float* x     = (const float*)d_in[0];
    const float* W     = (const float*)d_in[1];
    const float* gamma = (const float*)d_in[2];
    const float* beta  = (const float*)d_in[3];
    float* out = (float*)d_out;

    zero_stats_k<<<1, 64>>>();
    xx_k<<<(BB * NP) / 256, 256>>>(x);
    ac_k<<<dim3(NP / 128, BB), 256>>>(x, W);
    gram_k<<<dim3(NP / 128, NP / 128, BB), 256>>>(x);
    select_k<<<(BB * NP) / 8, 256>>>();
    maxmin_k<<<(BB * NP) / 4, 256>>>();
    finalize_k<<<1, 64>>>(gamma, beta);
    out_k<<<dim3(NP / 64, BB), 256>>>(out);
}